// round 14
// baseline (speedup 1.0000x reference)
#include <cuda_runtime.h>
#include <cuda_fp16.h>
#include <math.h>

// RenderNet volume rendering — round 14: R13 bodies + PDL overlap.
// K1 (weights): 1024x64, 1 ray/thread, 16-z double-buffered pipeline, fp16
//   weights shfl-packed -> even-lane STG.32. Calls
//   cudaTriggerProgrammaticLaunchCompletion() at entry so K2 may launch early.
// K2 (composite): FROZEN R9/R12 body (740x256, 5 CTA/SM, 6.39TB/s). Launched
//   with ProgrammaticStreamSerialization; every thread calls
//   cudaGridDependencySynchronize() before reading g_wbuf (correctness is
//   carried by this sync, not by trigger timing).
// out: [0]=loss, [1..1+CN)=rgb_e, [1+CN..1+2CN)=feat_e, [..+N)=acc_e
// (out+1 only 4B-aligned -> scalar output stores).

#define RN_C 32
#define RN_Z 64
#define RN_N 65536
#define RAW_NOISE_STD 0.1f
#define FAR_DIST 1e10f

#define K2_GRID 740            // 5 CTAs/SM * 148 SMs, single wave
#define K2_THREADS 256
#define K2_NWARPS (K2_GRID * K2_THREADS / 32)       // 5920
#define K2_WARPJOBS ((RN_C / 4) * (RN_N / 4 / 8))   // 16384

__device__ __half g_wbuf[RN_Z * RN_N];   // weights [z][n], fp16, 8MB

// ---------------- K1: weights, 16-z double-buffered pipeline ----------------
__global__ void __launch_bounds__(64)
rn_weights(const float* __restrict__ occ,
           const float* __restrict__ z_dist,
           const float* __restrict__ noise,
           float* __restrict__ out)
{
    // Let the dependent composite kernel launch immediately; it gates itself
    // on grid completion via cudaGridDependencySynchronize().
    cudaTriggerProgrammaticLaunchCompletion();

    __shared__ float s_dist[RN_Z];
    const int tid = threadIdx.x;
    s_dist[tid] = (tid < RN_Z - 1) ? (z_dist[tid + 1] - z_dist[tid]) : FAR_DIST;
    __syncthreads();

    const int n = blockIdx.x * 64 + tid;
    const bool even = ((n & 1) == 0);
    const float4* np4 = (const float4*)(noise + (size_t)n * RN_Z);
    const float*  occp = occ + n;

    float trans = 1.0f;
    float wsum  = 0.0f;

    float  ov[2][16];
    float4 nq[2][4];

    // prologue: load chunk 0
#pragma unroll
    for (int j = 0; j < 16; ++j)
        ov[0][j] = __ldcs(occp + (size_t)j * RN_N);
#pragma unroll
    for (int j = 0; j < 4; ++j)
        nq[0][j] = __ldcs(np4 + j);

#pragma unroll
    for (int zc = 0; zc < RN_Z / 16; ++zc) {       // 4 chunks of 16 z
        const int cur = zc & 1;
        const int nxt = cur ^ 1;

        if (zc < RN_Z / 16 - 1) {
#pragma unroll
            for (int j = 0; j < 16; ++j)
                ov[nxt][j] = __ldcs(occp + (size_t)((zc + 1) * 16 + j) * RN_N);
#pragma unroll
            for (int j = 0; j < 4; ++j)
                nq[nxt][j] = __ldcs(np4 + (zc + 1) * 4 + j);
        }

        float nv[16];
#pragma unroll
        for (int j = 0; j < 4; ++j) {
            nv[j * 4 + 0] = nq[cur][j].x; nv[j * 4 + 1] = nq[cur][j].y;
            nv[j * 4 + 2] = nq[cur][j].z; nv[j * 4 + 3] = nq[cur][j].w;
        }
#pragma unroll
        for (int j = 0; j < 16; ++j) {
            int z = zc * 16 + j;
            float raw = fmaxf(fmaf(nv[j], RAW_NOISE_STD, ov[cur][j]), 0.0f);
            float alpha = 1.0f - expf(-raw * s_dist[z]);
            float w = alpha * trans;
            trans *= (1.0f - alpha + 1e-10f);
            wsum  += w;
            float wnext = __shfl_down_sync(0xffffffffu, w, 1);
            if (even)
                *(__half2*)&g_wbuf[(size_t)z * RN_N + n] =
                    __floats2half2_rn(w, wnext);     // STG.32, even lanes
        }
    }

    float* am = out + 1 + 2 * (size_t)RN_C * RN_N;
    am[n] = fminf(fmaxf(wsum, 0.0f), 1.0f);
    if (n == 0) out[0] = 0.0f;
}

// ---------------- K2: composite (frozen body + grid-dependency gate) ----------------
__global__ void __launch_bounds__(K2_THREADS, 5)
rn_composite(const float* __restrict__ feat,
             float* __restrict__ out)
{
    const int wid0 = (blockIdx.x * K2_THREADS + threadIdx.x) >> 5;
    const int lane = threadIdx.x & 31;
    const int c2   = lane >> 3;     // 0..3 channel within group
    const int q8   = lane & 7;      // 0..7 quad within group

    float* rgb = out + 1;
    float* fe  = out + 1 + (size_t)RN_C * RN_N;
    const size_t ZN = (size_t)RN_Z * (size_t)RN_N;

    // Wait for rn_weights' grid (incl. memory flush) before reading g_wbuf.
    cudaGridDependencySynchronize();

    for (int wj = wid0; wj < K2_WARPJOBS; wj += K2_NWARPS) {
        const int cg = wj >> 11;               // 0..7 channel group
        const int qg = wj & 2047;              // 0..2047 quad group
        const int c  = cg * 4 + c2;            // channel 0..31
        const int n0 = (qg * 8 + q8) * 4;      // ray start

        const float*  fp = feat + (size_t)c * ZN + n0;
        const __half* wp = g_wbuf + n0;

        float4 a = {0.f, 0.f, 0.f, 0.f};
#pragma unroll 4
        for (int z = 0; z < RN_Z; ++z) {
            uint2 wraw = __ldg((const uint2*)(wp + (size_t)z * RN_N));
            const __half2* wh = (const __half2*)&wraw;
            float2 w01 = __half22float2(wh[0]);
            float2 w23 = __half22float2(wh[1]);
            float4 v = __ldcs((const float4*)(fp + (size_t)z * RN_N));
            a.x = fmaf(w01.x, v.x, a.x);
            a.y = fmaf(w01.y, v.y, a.y);
            a.z = fmaf(w23.x, v.z, a.z);
            a.w = fmaf(w23.y, v.w, a.w);
        }

        const size_t o0 = (size_t)c * RN_N + n0;
        float av[4] = {a.x, a.y, a.z, a.w};
#pragma unroll
        for (int j = 0; j < 4; ++j) {
            fe[o0 + j]  = av[j];
            rgb[o0 + j] = 1.0f / (1.0f + expf(-av[j])) - 0.5f;
        }
    }
}

// ---------------- generic fallback (any Z/N) ----------------
__global__ void __launch_bounds__(256)
rendernet_generic(const float* __restrict__ feat,
                  const float* __restrict__ occ,
                  const float* __restrict__ z_dist,
                  const float* __restrict__ noise,
                  float* __restrict__ out,
                  int Z, int N)
{
    extern __shared__ float s_d[];
    int tid = threadIdx.x;
    if (tid < Z)
        s_d[tid] = (tid < Z - 1) ? (z_dist[tid + 1] - z_dist[tid]) : FAR_DIST;
    __syncthreads();

    int n = blockIdx.x * blockDim.x + tid;
    if (n >= N) return;

    float acc[RN_C];
#pragma unroll
    for (int c = 0; c < RN_C; ++c) acc[c] = 0.0f;

    const float* occp   = occ + n;
    const float* noisep = noise + (size_t)n * Z;
    const float* featp  = feat + n;
    const size_t ZN = (size_t)Z * (size_t)N;

    float trans = 1.0f, wsum = 0.0f;
    for (int z = 0; z < Z; ++z) {
        float raw = fmaxf(fmaf(noisep[z], RAW_NOISE_STD, occp[(size_t)z * N]), 0.0f);
        float alpha = 1.0f - expf(-raw * s_d[z]);
        float w = alpha * trans;
        trans *= (1.0f - alpha + 1e-10f);
        wsum += w;
        const float* fz = featp + (size_t)z * N;
#pragma unroll
        for (int c = 0; c < RN_C; ++c)
            acc[c] = fmaf(w, fz[(size_t)c * ZN], acc[c]);
    }
    float* rgb = out + 1;
    float* fe  = out + 1 + (size_t)RN_C * N;
    float* am  = out + 1 + 2 * (size_t)RN_C * N;
#pragma unroll
    for (int c = 0; c < RN_C; ++c) {
        float f = acc[c];
        fe[(size_t)c * N + n]  = f;
        rgb[(size_t)c * N + n] = 1.0f / (1.0f + expf(-f)) - 0.5f;
    }
    am[n] = fminf(fmaxf(wsum, 0.0f), 1.0f);
    if (n == 0) out[0] = 0.0f;
}

extern "C" void kernel_launch(void* const* d_in, const int* in_sizes, int n_in,
                              void* d_out, int out_size)
{
    const float* feat   = (const float*)d_in[0];
    const float* occ    = (const float*)d_in[1];
    const float* z_dist = (const float*)d_in[2];
    const float* noise  = (const float*)d_in[3];
    float* out = (float*)d_out;

    int Z = in_sizes[2];
    int N = in_sizes[1] / Z;

    if (Z == RN_Z && N == RN_N) {
        rn_weights<<<RN_N / 64, 64>>>(occ, z_dist, noise, out);

        // K2 with programmatic stream serialization: launches while K1 runs;
        // K2 gates itself via cudaGridDependencySynchronize().
        cudaLaunchConfig_t cfg = {};
        cfg.gridDim  = dim3(K2_GRID, 1, 1);
        cfg.blockDim = dim3(K2_THREADS, 1, 1);
        cfg.dynamicSmemBytes = 0;
        cfg.stream = 0;   // same (legacy) stream the harness captures
        cudaLaunchAttribute attrs[1];
        attrs[0].id = cudaLaunchAttributeProgrammaticStreamSerialization;
        attrs[0].val.programmaticStreamSerializationAllowed = 1;
        cfg.attrs = attrs;
        cfg.numAttrs = 1;
        cudaLaunchKernelEx(&cfg, rn_composite, feat, out);
    } else {
        int block = 256;
        int grid = (N + block - 1) / block;
        rendernet_generic<<<grid, block, Z * sizeof(float)>>>(feat, occ, z_dist, noise, out, Z, N);
    }
}

// round 15
// speedup vs baseline: 1.0278x; 1.0278x over previous
#include <cuda_runtime.h>
#include <cuda_fp16.h>
#include <math.h>

// RenderNet volume rendering — round 15: R13 structure (PDL reverted),
// fast-math transcendentals.
// K1: 1024x64, 1 ray/thread, 16-z double-buffered pipeline; __expf (MUFU EX2)
//     in the alpha computation; fp16 weights shfl-packed -> even-lane STG.32.
// K2: FROZEN R9/R12 body (740x256, 5 CTA/SM, 6.39TB/s, at traffic floor);
//     sigmoid via __expf + __fdividef (error ~1e-6, threshold 1e-3).
// out: [0]=loss, [1..1+CN)=rgb_e, [1+CN..1+2CN)=feat_e, [..+N)=acc_e
// (out+1 only 4B-aligned -> scalar output stores).

#define RN_C 32
#define RN_Z 64
#define RN_N 65536
#define RAW_NOISE_STD 0.1f
#define FAR_DIST 1e10f

#define K2_GRID 740            // 5 CTAs/SM * 148 SMs, single wave
#define K2_THREADS 256
#define K2_NWARPS (K2_GRID * K2_THREADS / 32)       // 5920
#define K2_WARPJOBS ((RN_C / 4) * (RN_N / 4 / 8))   // 16384

__device__ __half g_wbuf[RN_Z * RN_N];   // weights [z][n], fp16, 8MB

// ---------------- K1: weights, 16-z double-buffered pipeline ----------------
__global__ void __launch_bounds__(64)
rn_weights(const float* __restrict__ occ,
           const float* __restrict__ z_dist,
           const float* __restrict__ noise,
           float* __restrict__ out)
{
    __shared__ float s_dist[RN_Z];
    const int tid = threadIdx.x;
    s_dist[tid] = (tid < RN_Z - 1) ? (z_dist[tid + 1] - z_dist[tid]) : FAR_DIST;
    __syncthreads();

    const int n = blockIdx.x * 64 + tid;
    const bool even = ((n & 1) == 0);
    const float4* np4 = (const float4*)(noise + (size_t)n * RN_Z);
    const float*  occp = occ + n;

    float trans = 1.0f;
    float wsum  = 0.0f;

    float  ov[2][16];
    float4 nq[2][4];

    // prologue: load chunk 0
#pragma unroll
    for (int j = 0; j < 16; ++j)
        ov[0][j] = __ldcs(occp + (size_t)j * RN_N);
#pragma unroll
    for (int j = 0; j < 4; ++j)
        nq[0][j] = __ldcs(np4 + j);

#pragma unroll
    for (int zc = 0; zc < RN_Z / 16; ++zc) {       // 4 chunks of 16 z
        const int cur = zc & 1;
        const int nxt = cur ^ 1;

        // issue next chunk's loads FIRST (in flight during exp chain)
        if (zc < RN_Z / 16 - 1) {
#pragma unroll
            for (int j = 0; j < 16; ++j)
                ov[nxt][j] = __ldcs(occp + (size_t)((zc + 1) * 16 + j) * RN_N);
#pragma unroll
            for (int j = 0; j < 4; ++j)
                nq[nxt][j] = __ldcs(np4 + (zc + 1) * 4 + j);
        }

        float nv[16];
#pragma unroll
        for (int j = 0; j < 4; ++j) {
            nv[j * 4 + 0] = nq[cur][j].x; nv[j * 4 + 1] = nq[cur][j].y;
            nv[j * 4 + 2] = nq[cur][j].z; nv[j * 4 + 3] = nq[cur][j].w;
        }
#pragma unroll
        for (int j = 0; j < 16; ++j) {
            int z = zc * 16 + j;
            float raw = fmaxf(fmaf(nv[j], RAW_NOISE_STD, ov[cur][j]), 0.0f);
            float alpha = 1.0f - __expf(-raw * s_dist[z]);   // MUFU EX2 path
            float w = alpha * trans;
            trans *= (1.0f - alpha + 1e-10f);
            wsum  += w;
            float wnext = __shfl_down_sync(0xffffffffu, w, 1);
            if (even)
                *(__half2*)&g_wbuf[(size_t)z * RN_N + n] =
                    __floats2half2_rn(w, wnext);     // STG.32, even lanes
        }
    }

    float* am = out + 1 + 2 * (size_t)RN_C * RN_N;
    am[n] = fminf(fmaxf(wsum, 0.0f), 1.0f);
    if (n == 0) out[0] = 0.0f;
}

// ---------------- K2: composite (frozen body, fast sigmoid) ----------------
__global__ void __launch_bounds__(K2_THREADS, 5)
rn_composite(const float* __restrict__ feat,
             float* __restrict__ out)
{
    const int wid0 = (blockIdx.x * K2_THREADS + threadIdx.x) >> 5;
    const int lane = threadIdx.x & 31;
    const int c2   = lane >> 3;     // 0..3 channel within group
    const int q8   = lane & 7;      // 0..7 quad within group

    float* rgb = out + 1;
    float* fe  = out + 1 + (size_t)RN_C * RN_N;
    const size_t ZN = (size_t)RN_Z * (size_t)RN_N;

    for (int wj = wid0; wj < K2_WARPJOBS; wj += K2_NWARPS) {
        const int cg = wj >> 11;               // 0..7 channel group
        const int qg = wj & 2047;              // 0..2047 quad group
        const int c  = cg * 4 + c2;            // channel 0..31
        const int n0 = (qg * 8 + q8) * 4;      // ray start

        const float*  fp = feat + (size_t)c * ZN + n0;
        const __half* wp = g_wbuf + n0;

        float4 a = {0.f, 0.f, 0.f, 0.f};
#pragma unroll 4
        for (int z = 0; z < RN_Z; ++z) {
            uint2 wraw = __ldg((const uint2*)(wp + (size_t)z * RN_N));
            const __half2* wh = (const __half2*)&wraw;
            float2 w01 = __half22float2(wh[0]);
            float2 w23 = __half22float2(wh[1]);
            float4 v = __ldcs((const float4*)(fp + (size_t)z * RN_N));
            a.x = fmaf(w01.x, v.x, a.x);
            a.y = fmaf(w01.y, v.y, a.y);
            a.z = fmaf(w23.x, v.z, a.z);
            a.w = fmaf(w23.y, v.w, a.w);
        }

        const size_t o0 = (size_t)c * RN_N + n0;
        float av[4] = {a.x, a.y, a.z, a.w};
#pragma unroll
        for (int j = 0; j < 4; ++j) {
            fe[o0 + j]  = av[j];
            rgb[o0 + j] = __fdividef(1.0f, 1.0f + __expf(-av[j])) - 0.5f;
        }
    }
}

// ---------------- generic fallback (any Z/N) ----------------
__global__ void __launch_bounds__(256)
rendernet_generic(const float* __restrict__ feat,
                  const float* __restrict__ occ,
                  const float* __restrict__ z_dist,
                  const float* __restrict__ noise,
                  float* __restrict__ out,
                  int Z, int N)
{
    extern __shared__ float s_d[];
    int tid = threadIdx.x;
    if (tid < Z)
        s_d[tid] = (tid < Z - 1) ? (z_dist[tid + 1] - z_dist[tid]) : FAR_DIST;
    __syncthreads();

    int n = blockIdx.x * blockDim.x + tid;
    if (n >= N) return;

    float acc[RN_C];
#pragma unroll
    for (int c = 0; c < RN_C; ++c) acc[c] = 0.0f;

    const float* occp   = occ + n;
    const float* noisep = noise + (size_t)n * Z;
    const float* featp  = feat + n;
    const size_t ZN = (size_t)Z * (size_t)N;

    float trans = 1.0f, wsum = 0.0f;
    for (int z = 0; z < Z; ++z) {
        float raw = fmaxf(fmaf(noisep[z], RAW_NOISE_STD, occp[(size_t)z * N]), 0.0f);
        float alpha = 1.0f - expf(-raw * s_d[z]);
        float w = alpha * trans;
        trans *= (1.0f - alpha + 1e-10f);
        wsum += w;
        const float* fz = featp + (size_t)z * N;
#pragma unroll
        for (int c = 0; c < RN_C; ++c)
            acc[c] = fmaf(w, fz[(size_t)c * ZN], acc[c]);
    }
    float* rgb = out + 1;
    float* fe  = out + 1 + (size_t)RN_C * N;
    float* am  = out + 1 + 2 * (size_t)RN_C * N;
#pragma unroll
    for (int c = 0; c < RN_C; ++c) {
        float f = acc[c];
        fe[(size_t)c * N + n]  = f;
        rgb[(size_t)c * N + n] = 1.0f / (1.0f + expf(-f)) - 0.5f;
    }
    am[n] = fminf(fmaxf(wsum, 0.0f), 1.0f);
    if (n == 0) out[0] = 0.0f;
}

extern "C" void kernel_launch(void* const* d_in, const int* in_sizes, int n_in,
                              void* d_out, int out_size)
{
    const float* feat   = (const float*)d_in[0];
    const float* occ    = (const float*)d_in[1];
    const float* z_dist = (const float*)d_in[2];
    const float* noise  = (const float*)d_in[3];
    float* out = (float*)d_out;

    int Z = in_sizes[2];
    int N = in_sizes[1] / Z;

    if (Z == RN_Z && N == RN_N) {
        rn_weights<<<RN_N / 64, 64>>>(occ, z_dist, noise, out);
        rn_composite<<<K2_GRID, K2_THREADS>>>(feat, out);
    } else {
        int block = 256;
        int grid = (N + block - 1) / block;
        rendernet_generic<<<grid, block, Z * sizeof(float)>>>(feat, occ, z_dist, noise, out, Z, N);
    }
}

// round 16
// speedup vs baseline: 1.0355x; 1.0075x over previous
#include <cuda_runtime.h>
#include <cuda_fp16.h>
#include <math.h>

// RenderNet volume rendering — round 16.
// K1: 1024x128, TWO threads per ray (split-scan): even lane does z[0:32),
//     odd lane z[32:64) with local trans, rescaled by partner's total product
//     P_low via shfl (algebraically identical to sequential cumprod, incl.
//     +1e-10 terms). Halves the serial MUFU chain, doubles warps/SM.
//     __expf; fp16 weights packed half2 across the ray pair (shfl by 2).
// K2: FROZEN R15 body (740x256, 5 CTA/SM, fast sigmoid) + __stcs output
//     stores so the 16MB of writes don't evict the L2-resident wbuf.
// out: [0]=loss, [1..1+CN)=rgb_e, [1+CN..1+2CN)=feat_e, [..+N)=acc_e
// (out+1 only 4B-aligned -> scalar output stores).

#define RN_C 32
#define RN_Z 64
#define RN_N 65536
#define RAW_NOISE_STD 0.1f
#define FAR_DIST 1e10f

#define K1_THREADS 128
#define K1_GRID ((RN_N * 2) / K1_THREADS)            // 1024

#define K2_GRID 740            // 5 CTAs/SM * 148 SMs, single wave
#define K2_THREADS 256
#define K2_NWARPS (K2_GRID * K2_THREADS / 32)       // 5920
#define K2_WARPJOBS ((RN_C / 4) * (RN_N / 4 / 8))   // 16384

__device__ __half g_wbuf[RN_Z * RN_N];   // weights [z][n], fp16, 8MB

// ---------------- K1: weights, split-scan 2 threads/ray ----------------
__global__ void __launch_bounds__(K1_THREADS)
rn_weights(const float* __restrict__ occ,
           const float* __restrict__ z_dist,
           const float* __restrict__ noise,
           float* __restrict__ out)
{
    __shared__ float s_dist[RN_Z];
    const int tid = threadIdx.x;
    if (tid < RN_Z)
        s_dist[tid] = (tid < RN_Z - 1) ? (z_dist[tid + 1] - z_dist[tid]) : FAR_DIST;
    __syncthreads();

    const int g     = blockIdx.x * K1_THREADS + tid;
    const int n     = g >> 1;          // ray
    const int h     = g & 1;           // half: 0 -> z[0:32), 1 -> z[32:64)
    const int zbase = h << 5;
    const int lane  = tid & 31;

    // noise: 8 float4 = 128B contiguous (this thread's half of row n)
    const float4* np4 = (const float4*)(noise + (size_t)n * RN_Z + zbase);
    float4 nq[8];
#pragma unroll
    for (int j = 0; j < 8; ++j) nq[j] = __ldcs(np4 + j);

    // occ: 32 independent scalars (even lanes z=j, odd lanes z=32+j; each
    // group of same-half lanes is contiguous in n -> 64B sectors)
    float ov[32];
#pragma unroll
    for (int j = 0; j < 32; ++j)
        ov[j] = __ldcs(occ + (size_t)(zbase + j) * RN_N + n);

    float nv[32];
#pragma unroll
    for (int j = 0; j < 8; ++j) {
        nv[4 * j + 0] = nq[j].x; nv[4 * j + 1] = nq[j].y;
        nv[4 * j + 2] = nq[j].z; nv[4 * j + 3] = nq[j].w;
    }

    // local 32-step recurrence (trans starts at 1 in both halves)
    float trans = 1.0f, wsum = 0.0f;
    float w[32];
#pragma unroll
    for (int j = 0; j < 32; ++j) {
        float raw   = fmaxf(fmaf(nv[j], RAW_NOISE_STD, ov[j]), 0.0f);
        float alpha = 1.0f - __expf(-raw * s_dist[zbase + j]);
        w[j] = alpha * trans;
        trans *= (1.0f - alpha + 1e-10f);
        wsum += w[j];
    }

    // pair exchange: even lane's total product rescales the odd half
    float P_low   = __shfl_sync(0xffffffffu, trans, lane & ~1); // from even partner
    float wsum_hi = __shfl_sync(0xffffffffu, wsum,  lane |  1); // from odd partner
    const float scale = h ? P_low : 1.0f;

    if (h == 0) {
        float am = wsum + trans * wsum_hi;    // trans == P_low on even lane
        float* amp = out + 1 + 2 * (size_t)RN_C * RN_N;
        amp[n] = fminf(fmaxf(am, 0.0f), 1.0f);
    }

    // scale + pack half2 across ray pair: lanes l (ray even) and l+2 share h
#pragma unroll
    for (int j = 0; j < 32; ++j) {
        float ws      = w[j] * scale;
        float ws_next = __shfl_down_sync(0xffffffffu, ws, 2);
        if ((tid & 2) == 0)   // even ray -> store pair (n, n+1)
            *(__half2*)&g_wbuf[(size_t)(zbase + j) * RN_N + n] =
                __floats2half2_rn(ws, ws_next);
    }

    if (g == 0) out[0] = 0.0f;
}

// ---------------- K2: composite (frozen body + streaming output stores) ----------------
__global__ void __launch_bounds__(K2_THREADS, 5)
rn_composite(const float* __restrict__ feat,
             float* __restrict__ out)
{
    const int wid0 = (blockIdx.x * K2_THREADS + threadIdx.x) >> 5;
    const int lane = threadIdx.x & 31;
    const int c2   = lane >> 3;     // 0..3 channel within group
    const int q8   = lane & 7;      // 0..7 quad within group

    float* rgb = out + 1;
    float* fe  = out + 1 + (size_t)RN_C * RN_N;
    const size_t ZN = (size_t)RN_Z * (size_t)RN_N;

    for (int wj = wid0; wj < K2_WARPJOBS; wj += K2_NWARPS) {
        const int cg = wj >> 11;               // 0..7 channel group
        const int qg = wj & 2047;              // 0..2047 quad group
        const int c  = cg * 4 + c2;            // channel 0..31
        const int n0 = (qg * 8 + q8) * 4;      // ray start

        const float*  fp = feat + (size_t)c * ZN + n0;
        const __half* wp = g_wbuf + n0;

        float4 a = {0.f, 0.f, 0.f, 0.f};
#pragma unroll 4
        for (int z = 0; z < RN_Z; ++z) {
            uint2 wraw = __ldg((const uint2*)(wp + (size_t)z * RN_N));
            const __half2* wh = (const __half2*)&wraw;
            float2 w01 = __half22float2(wh[0]);
            float2 w23 = __half22float2(wh[1]);
            float4 v = __ldcs((const float4*)(fp + (size_t)z * RN_N));
            a.x = fmaf(w01.x, v.x, a.x);
            a.y = fmaf(w01.y, v.y, a.y);
            a.z = fmaf(w23.x, v.z, a.z);
            a.w = fmaf(w23.y, v.w, a.w);
        }

        const size_t o0 = (size_t)c * RN_N + n0;
        float av[4] = {a.x, a.y, a.z, a.w};
#pragma unroll
        for (int j = 0; j < 4; ++j) {
            __stcs(&fe[o0 + j], av[j]);
            __stcs(&rgb[o0 + j],
                   __fdividef(1.0f, 1.0f + __expf(-av[j])) - 0.5f);
        }
    }
}

// ---------------- generic fallback (any Z/N) ----------------
__global__ void __launch_bounds__(256)
rendernet_generic(const float* __restrict__ feat,
                  const float* __restrict__ occ,
                  const float* __restrict__ z_dist,
                  const float* __restrict__ noise,
                  float* __restrict__ out,
                  int Z, int N)
{
    extern __shared__ float s_d[];
    int tid = threadIdx.x;
    if (tid < Z)
        s_d[tid] = (tid < Z - 1) ? (z_dist[tid + 1] - z_dist[tid]) : FAR_DIST;
    __syncthreads();

    int n = blockIdx.x * blockDim.x + tid;
    if (n >= N) return;

    float acc[RN_C];
#pragma unroll
    for (int c = 0; c < RN_C; ++c) acc[c] = 0.0f;

    const float* occp   = occ + n;
    const float* noisep = noise + (size_t)n * Z;
    const float* featp  = feat + n;
    const size_t ZN = (size_t)Z * (size_t)N;

    float trans = 1.0f, wsum = 0.0f;
    for (int z = 0; z < Z; ++z) {
        float raw = fmaxf(fmaf(noisep[z], RAW_NOISE_STD, occp[(size_t)z * N]), 0.0f);
        float alpha = 1.0f - expf(-raw * s_d[z]);
        float w = alpha * trans;
        trans *= (1.0f - alpha + 1e-10f);
        wsum += w;
        const float* fz = featp + (size_t)z * N;
#pragma unroll
        for (int c = 0; c < RN_C; ++c)
            acc[c] = fmaf(w, fz[(size_t)c * ZN], acc[c]);
    }
    float* rgb = out + 1;
    float* fe  = out + 1 + (size_t)RN_C * N;
    float* am  = out + 1 + 2 * (size_t)RN_C * N;
#pragma unroll
    for (int c = 0; c < RN_C; ++c) {
        float f = acc[c];
        fe[(size_t)c * N + n]  = f;
        rgb[(size_t)c * N + n] = 1.0f / (1.0f + expf(-f)) - 0.5f;
    }
    am[n] = fminf(fmaxf(wsum, 0.0f), 1.0f);
    if (n == 0) out[0] = 0.0f;
}

extern "C" void kernel_launch(void* const* d_in, const int* in_sizes, int n_in,
                              void* d_out, int out_size)
{
    const float* feat   = (const float*)d_in[0];
    const float* occ    = (const float*)d_in[1];
    const float* z_dist = (const float*)d_in[2];
    const float* noise  = (const float*)d_in[3];
    float* out = (float*)d_out;

    int Z = in_sizes[2];
    int N = in_sizes[1] / Z;

    if (Z == RN_Z && N == RN_N) {
        rn_weights<<<K1_GRID, K1_THREADS>>>(occ, z_dist, noise, out);
        rn_composite<<<K2_GRID, K2_THREADS>>>(feat, out);
    } else {
        int block = 256;
        int grid = (N + block - 1) / block;
        rendernet_generic<<<grid, block, Z * sizeof(float)>>>(feat, occ, z_dist, noise, out, Z, N);
    }
}